// round 15
// baseline (speedup 1.0000x reference)
#include <cuda_runtime.h>
#include <cuda_fp16.h>
#include <cstdint>

// Problem constants
#define NB   4096   // batch B
#define NM   8192   // memory rows M
#define ND   1024   // dim D
#define NOUT 1000   // output classes
#define NOUTP 1024  // padded output cols
#define NH   4096   // 4*D hidden
#define N2D  2048   // 2*D concat width

// -------- scratch (device globals; no allocation allowed) --------
__device__ float g_xinv[NB];
__device__ float g_yinv[NM];
__device__ half  g_sim[(size_t)NB * NM];        // 64 MB (fp16 sims)
__device__ half  g_cat_h[(size_t)NB * N2D];     // 16 MB  [enc | mv] rounded
__device__ half  g_mem_h[(size_t)NM * ND];      // 16 MB
__device__ half  g_hid_h[(size_t)NB * NH];      // 32 MB
__device__ half  g_w1_h[(size_t)NH * N2D];      // 16 MB
__device__ half  g_w2_h[(size_t)NOUTP * NH];    // 8 MB (padded)

// ---------------------------------------------------------------
// helpers
// ---------------------------------------------------------------
__device__ __forceinline__ uint32_t cvta_smem(const void* p) {
    uint32_t a;
    asm("{ .reg .u64 t; cvta.to.shared.u64 t, %1; cvt.u32.u64 %0, t; }"
        : "=r"(a) : "l"(p));
    return a;
}

__device__ __forceinline__ void cp16(uint32_t dst, const void* src) {
    asm volatile("cp.async.cg.shared.global [%0], [%1], 16;" :: "r"(dst), "l"(src));
}

__device__ __forceinline__ void mma_fp16(float* d, const uint32_t* a, const uint32_t* b) {
    asm volatile(
        "mma.sync.aligned.m16n8k16.row.col.f32.f16.f16.f32 "
        "{%0,%1,%2,%3}, {%4,%5,%6,%7}, {%8,%9}, {%0,%1,%2,%3};"
        : "+f"(d[0]), "+f"(d[1]), "+f"(d[2]), "+f"(d[3])
        : "r"(a[0]), "r"(a[1]), "r"(a[2]), "r"(a[3]), "r"(b[0]), "r"(b[1]));
}

__device__ __forceinline__ void ldsm_x4(uint32_t* r, uint32_t addr) {
    asm volatile("ldmatrix.sync.aligned.m8n8.x4.shared.b16 {%0,%1,%2,%3}, [%4];"
                 : "=r"(r[0]), "=r"(r[1]), "=r"(r[2]), "=r"(r[3]) : "r"(addr));
}

// ---------------------------------------------------------------
// block reduce (256 threads)
// ---------------------------------------------------------------
__device__ __forceinline__ float blockReduceSum256(float v, float* red) {
    __syncthreads();
    #pragma unroll
    for (int o = 16; o > 0; o >>= 1) v += __shfl_down_sync(0xffffffffu, v, o);
    int warp = threadIdx.x >> 5, lane = threadIdx.x & 31;
    if (lane == 0) red[warp] = v;
    __syncthreads();
    if (warp == 0) {
        v = (lane < 8) ? red[lane] : 0.0f;
        #pragma unroll
        for (int o = 4; o > 0; o >>= 1) v += __shfl_down_sync(0xffffffffu, v, o);
        if (lane == 0) red[0] = v;
    }
    __syncthreads();
    return red[0];
}

// ---------------------------------------------------------------
// fused prologue: one launch covers
//   [0, 4096)        enc rows:  1/||x|| + fp16 round -> cat left
//   [4096, 12288)    mem rows:  1/||y|| + fp16 round
//   [12288, 20480)   fc1w round (1024 floats per block)
//   [20480, 21504)   fc2w round + zero-pad row
// ---------------------------------------------------------------
#define PREP_ENC_END 4096
#define PREP_MEM_END 12288
#define PREP_W1_END  20480
#define PREP_BLOCKS  21504

__global__ __launch_bounds__(256) void prep_kernel(
    const float* __restrict__ enc, const float* __restrict__ mem,
    const float* __restrict__ fc1w, const float* __restrict__ fc2w)
{
    __shared__ float red[8];
    const int bid = blockIdx.x, tid = threadIdx.x;

    if (bid < PREP_ENC_END) {
        const int row = bid;
        float4 v = ((const float4*)(enc + (size_t)row * ND))[tid];
        float s = v.x*v.x + v.y*v.y + v.z*v.z + v.w*v.w;
        s = blockReduceSum256(s, red);
        if (tid == 0) g_xinv[row] = rsqrtf(s + 1e-6f);
        half* ph = g_cat_h + (size_t)row * N2D + tid * 4;
        ph[0] = __float2half_rn(v.x); ph[1] = __float2half_rn(v.y);
        ph[2] = __float2half_rn(v.z); ph[3] = __float2half_rn(v.w);
    } else if (bid < PREP_MEM_END) {
        const int row = bid - PREP_ENC_END;
        float4 v = ((const float4*)(mem + (size_t)row * ND))[tid];
        float s = v.x*v.x + v.y*v.y + v.z*v.z + v.w*v.w;
        s = blockReduceSum256(s, red);
        if (tid == 0) g_yinv[row] = rsqrtf(s + 1e-6f);
        half* ph = g_mem_h + (size_t)row * ND + tid * 4;
        ph[0] = __float2half_rn(v.x); ph[1] = __float2half_rn(v.y);
        ph[2] = __float2half_rn(v.z); ph[3] = __float2half_rn(v.w);
    } else if (bid < PREP_W1_END) {
        const size_t i = (size_t)(bid - PREP_MEM_END) * 256 + tid;
        float4 v = ((const float4*)fc1w)[i];
        half* p = g_w1_h + i * 4;
        p[0] = __float2half_rn(v.x); p[1] = __float2half_rn(v.y);
        p[2] = __float2half_rn(v.z); p[3] = __float2half_rn(v.w);
    } else {
        const int row = bid - PREP_W1_END;   // 0..1023
        #pragma unroll
        for (int lq = 0; lq < 4; ++lq) {
            int idx = tid + 256 * lq;
            float4 v = make_float4(0.f, 0.f, 0.f, 0.f);
            if (row < NOUT) v = ((const float4*)(fc2w + (size_t)row * NH))[idx];
            half* p = g_w2_h + (size_t)row * NH + idx * 4;
            p[0] = __float2half_rn(v.x); p[1] = __float2half_rn(v.y);
            p[2] = __float2half_rn(v.z); p[3] = __float2half_rn(v.w);
        }
    }
}

// ---------------------------------------------------------------
// single-pass fp16 GEMM (mma.sync.m16n8k16 + ldmatrix):
//   C[M,N] = A[M,K] @ B[N,K]^T, fp32 accum
// 128x128 CTA tile, BK=64, 3-stage cp.async pipeline, 2 CTAs/SM,
// 128 threads (4 warps 2x2, 64x64 warp tiles) -- halves LDSM
// redundancy (A and B each re-read only 2x) vs 8-warp layout.
// Coalesced tile loads (8 lanes per 128B row).
// EPI 0/1: smem-staged coalesced fp16 stores; EPI 2: guarded fp32.
// ---------------------------------------------------------------
#define BKE     64
#define ROW_B   144                      // 128 + 16 pad
#define A_T     (128 * ROW_B)            // 18432
#define B_T     (128 * ROW_B)            // 18432
#define STAGE_B (A_T + B_T)              // 36864
#define NSTAGE  3
#define GEMM_SMEM (NSTAGE * STAGE_B)     // 110592
#define OUT_SROW 136                     // staging stride in halves (272 B)

template<int EPI>
__global__ __launch_bounds__(128, 2) void tc_gemm(
    int N, int K, int lda, int ldb, int Nout,
    const half* __restrict__ A0, const half* __restrict__ B0,
    float* __restrict__ C, half* __restrict__ Ch,
    const float* __restrict__ xinv, const float* __restrict__ yinv,
    const float* __restrict__ bias)
{
    extern __shared__ __align__(1024) char smraw[];
    const uint32_t smemU = cvta_smem(smraw);

    const int tid  = threadIdx.x;
    const int lane = tid & 31;
    const int wid  = tid >> 5;
    const int wm   = wid & 1;          // 0..1 (64-row block)
    const int wn   = wid >> 1;         // 0..1 (64-col block)
    const int row0 = blockIdx.y * 128;
    const int col0 = blockIdx.x * 128;

    const int nkc = K / BKE;

    // Coalesced global->smem: 8 lanes per row (16B each); 128 threads cover
    // 16 rows per pass, 8 passes for 128 rows (A and B each).
    const int wr  = tid >> 3;          // 0..15 base row
    const int lc8 = tid & 7;
    const uint32_t aBase = smemU + wr * ROW_B + lc8 * 16;
    const uint32_t bBase = smemU + A_T + wr * ROW_B + lc8 * 16;

    auto do_load = [&](int ck, int s) {
        const uint32_t so = s * STAGE_B;
        const half* ga = A0 + (size_t)(row0 + wr) * lda + ck * BKE + lc8 * 8;
        const half* gb = B0 + (size_t)(col0 + wr) * ldb + ck * BKE + lc8 * 8;
        #pragma unroll
        for (int i = 0; i < 8; ++i) {
            cp16(aBase + so + i * (16 * ROW_B), ga + (size_t)(16 * i) * lda);
            cp16(bBase + so + i * (16 * ROW_B), gb + (size_t)(16 * i) * ldb);
        }
    };

    float acc[4][8][4];
    #pragma unroll
    for (int mt = 0; mt < 4; ++mt)
        #pragma unroll
        for (int nt = 0; nt < 8; ++nt)
            #pragma unroll
            for (int c = 0; c < 4; ++c) acc[mt][nt][c] = 0.0f;

    do_load(0, 0);
    asm volatile("cp.async.commit_group;" ::: "memory");
    do_load(1, 1);
    asm volatile("cp.async.commit_group;" ::: "memory");

    // ldmatrix lane bases
    const uint32_t aFragBase = smemU + (wm * 64 + (lane & 15)) * ROW_B + (lane >> 4) * 16;
    // B x4 covers two 8-col n-tiles per instruction
    const uint32_t bFragBase = smemU + A_T +
        (wn * 64 + (lane & 7) + ((lane >> 4) & 1) * 8) * ROW_B + ((lane >> 3) & 1) * 16;

    for (int it = 0; it < nkc; ++it) {
        if (it + 2 < nkc) {
            asm volatile("cp.async.wait_group 1;" ::: "memory");
        } else {
            asm volatile("cp.async.wait_group 0;" ::: "memory");
        }
        __syncthreads();
        if (it + 2 < nkc) {
            do_load(it + 2, (it + 2) % NSTAGE);
            asm volatile("cp.async.commit_group;" ::: "memory");
        }

        const uint32_t so = (it % NSTAGE) * STAGE_B;

        #pragma unroll
        for (int ks = 0; ks < 4; ++ks) {
            const uint32_t ko = ks * 32;
            uint32_t bfr[16];   // 8 n-tiles x 2 regs
            #pragma unroll
            for (int p = 0; p < 4; ++p)
                ldsm_x4(&bfr[4 * p], bFragBase + so + p * (16 * ROW_B) + ko);

            uint32_t afr[4][4];
            #pragma unroll
            for (int mt = 0; mt < 4; ++mt)
                ldsm_x4(afr[mt], aFragBase + so + mt * (16 * ROW_B) + ko);
            #pragma unroll
            for (int mt = 0; mt < 4; ++mt)
                #pragma unroll
                for (int nt = 0; nt < 8; ++nt)
                    mma_fp16(acc[mt][nt], afr[mt], &bfr[nt * 2]);
        }
    }

    // epilogue
    const int r = lane >> 2;
    const int q = lane & 3;

    if (EPI == 2) {
        #pragma unroll
        for (int mt = 0; mt < 4; ++mt) {
            const int gr0 = row0 + wm * 64 + mt * 16 + r;
            #pragma unroll
            for (int half_ = 0; half_ < 2; ++half_) {
                const int gr = gr0 + half_ * 8;
                #pragma unroll
                for (int nt = 0; nt < 8; ++nt) {
                    const int gc = col0 + wn * 64 + nt * 8 + q * 2;
                    if (gc < Nout) {
                        float2 o = make_float2(acc[mt][nt][half_ * 2 + 0] + bias[gc],
                                               acc[mt][nt][half_ * 2 + 1] + bias[gc + 1]);
                        *(float2*)(C + (size_t)gr * Nout + gc) = o;
                    }
                }
            }
        }
    } else {
        __syncthreads();
        half* stg = (half*)smraw;
        #pragma unroll
        for (int mt = 0; mt < 4; ++mt) {
            const int lr0 = wm * 64 + mt * 16 + r;
            #pragma unroll
            for (int half_ = 0; half_ < 2; ++half_) {
                const int lr = lr0 + half_ * 8;
                float xr = 0.0f;
                if (EPI == 0) xr = xinv[row0 + lr];
                #pragma unroll
                for (int nt = 0; nt < 8; ++nt) {
                    const int lcL = wn * 64 + nt * 8 + q * 2;
                    float v0 = acc[mt][nt][half_ * 2 + 0];
                    float v1 = acc[mt][nt][half_ * 2 + 1];
                    __half2 hh;
                    const int gc = col0 + lcL;
                    if (EPI == 0) {
                        hh.x = __float2half_rn(v0 * xr * yinv[gc]);
                        hh.y = __float2half_rn(v1 * xr * yinv[gc + 1]);
                    } else {
                        hh.x = __float2half_rn(fmaxf(v0 + bias[gc], 0.0f));
                        hh.y = __float2half_rn(fmaxf(v1 + bias[gc + 1], 0.0f));
                    }
                    *(__half2*)(stg + lr * OUT_SROW + lcL) = hh;
                }
            }
        }
        __syncthreads();
        // coalesced: 128 rows x 16 uint4 (256B/row), 128 threads
        #pragma unroll
        for (int i = 0; i < 16; ++i) {
            const int idx  = tid + i * 128;
            const int rrow = idx >> 4;
            const int slot = idx & 15;
            uint4 v = *(const uint4*)(stg + rrow * OUT_SROW + slot * 8);
            *(uint4*)(Ch + (size_t)(row0 + rrow) * N + col0 + slot * 8) = v;
        }
    }
}

// ---------------------------------------------------------------
// Fused sparsemax (Michelot, sort-free, register-resident) + sparse
// memory-vector gather.  z input is fp16 (g_sim); math in fp32 regs.
// ---------------------------------------------------------------
#define SPX_CAP 4096
__global__ __launch_bounds__(256) void sparsemax_mv_kernel(const float* __restrict__ mem) {
    __shared__ __align__(16) half zh[NM];    // 16 KB
    __shared__ unsigned short idxs[SPX_CAP]; // 8 KB
    __shared__ float redS[8];
    __shared__ float redC[8];
    __shared__ int   wtot[8];
    __shared__ int   wpre[8];
    __shared__ float tau_sh;
    __shared__ int   cprev_sh;
    __shared__ int   done_sh;

    const int row = blockIdx.x;
    const int tid = threadIdx.x;
    const int warp = tid >> 5, lane = tid & 31;

    float zr[32];
    {
        const uint4* src = (const uint4*)(g_sim + (size_t)row * NM);
        #pragma unroll
        for (int l = 0; l < 4; ++l) {
            uint4 raw = src[tid + l * 256];
            ((uint4*)zh)[tid + l * 256] = raw;
            const __half2* hp = (const __half2*)&raw;
            #pragma unroll
            for (int k = 0; k < 4; ++k) {
                float2 f = __half22float2(hp[k]);
                zr[l * 8 + 2 * k]     = f.x;
                zr[l * 8 + 2 * k + 1] = f.y;
            }
        }
    }
    __syncthreads();

    {
        float s = 0.0f;
        #pragma unroll
        for (int i = 0; i < 32; ++i) s += zr[i];
        s = blockReduceSum256(s, redS);
        if (tid == 0) {
            tau_sh = (s - 1.0f) / (float)NM;
            cprev_sh = NM;
            done_sh = 0;
        }
        __syncthreads();
    }

    for (int it = 0; it < 64; ++it) {
        float tau = tau_sh;
        float ls = 0.0f, lc = 0.0f;
        #pragma unroll
        for (int i = 0; i < 32; ++i)
            if (zr[i] > tau) { ls += zr[i]; lc += 1.0f; }
        #pragma unroll
        for (int o = 16; o > 0; o >>= 1) {
            ls += __shfl_down_sync(0xffffffffu, ls, o);
            lc += __shfl_down_sync(0xffffffffu, lc, o);
        }
        if (lane == 0) { redS[warp] = ls; redC[warp] = lc; }
        __syncthreads();
        if (tid == 0) {
            float S = 0.0f, Cc = 0.0f;
            #pragma unroll
            for (int w = 0; w < 8; ++w) { S += redS[w]; Cc += redC[w]; }
            int c = (int)(Cc + 0.5f);
            if (c == cprev_sh || c <= 0) done_sh = 1;
            else { cprev_sh = c; tau_sh = (S - 1.0f) / (float)c; }
        }
        __syncthreads();
        if (done_sh) break;
    }
    const float tau = tau_sh;

    int mycnt = 0;
    #pragma unroll
    for (int i = 0; i < 32; ++i)
        if (zr[i] > tau) mycnt++;

    int csum = mycnt;
    #pragma unroll
    for (int o = 1; o < 32; o <<= 1) {
        int n = __shfl_up_sync(0xffffffffu, csum, o);
        if (lane >= o) csum += n;
    }
    if (lane == 31) wtot[warp] = csum;
    __syncthreads();
    if (warp == 0 && lane < 8) {
        int t = wtot[lane];
        #pragma unroll
        for (int o = 1; o < 8; o <<= 1) {
            int n = __shfl_up_sync(0x000000ffu, t, o);
            if (lane >= o) t += n;
        }
        wpre[lane] = t;
    }
    __syncthreads();
    const int nnz = wpre[7];
    if (nnz <= SPX_CAP) {
        int off = (warp ? wpre[warp - 1] : 0) + csum - mycnt;
        #pragma unroll
        for (int l = 0; l < 4; ++l) {
            int base = 8 * (tid + l * 256);
            #pragma unroll
            for (int j = 0; j < 8; ++j)
                if (zr[l * 8 + j] > tau) idxs[off++] = (unsigned short)(base + j);
        }
    }
    __syncthreads();

    float4 acc = make_float4(0.f, 0.f, 0.f, 0.f);
    const float4* mem4 = (const float4*)mem;
    if (nnz <= SPX_CAP) {
        #pragma unroll 4
        for (int j = 0; j < nnz; ++j) {
            int m = idxs[j];
            float w = __half2float(zh[m]) - tau;
            float4 v = mem4[(size_t)m * 256 + tid];
            acc.x += w * v.x; acc.y += w * v.y;
            acc.z += w * v.z; acc.w += w * v.w;
        }
    } else {
        for (int m = 0; m < NM; ++m) {
            float w = __half2float(zh[m]) - tau;
            if (w > 0.0f) {
                float4 v = mem4[(size_t)m * 256 + tid];
                acc.x += w * v.x; acc.y += w * v.y;
                acc.z += w * v.z; acc.w += w * v.w;
            }
        }
    }
    half* ph = g_cat_h + (size_t)row * N2D + ND + tid * 4;
    ph[0] = __float2half_rn(acc.x); ph[1] = __float2half_rn(acc.y);
    ph[2] = __float2half_rn(acc.z); ph[3] = __float2half_rn(acc.w);
}

// ---------------------------------------------------------------
// launch
// ---------------------------------------------------------------
extern "C" void kernel_launch(void* const* d_in, const int* in_sizes, int n_in,
                              void* d_out, int out_size) {
    const float* enc  = (const float*)d_in[0];  // [4096,1024]
    const float* mem  = (const float*)d_in[1];  // [8192,1024]
    const float* fc1w = (const float*)d_in[2];  // [4096,2048]
    const float* fc1b = (const float*)d_in[3];  // [4096]
    const float* fc2w = (const float*)d_in[4];  // [1000,4096]
    const float* fc2b = (const float*)d_in[5];  // [1000]
    float* out = (float*)d_out;                 // [4096,1000]

    void *p_xinv, *p_yinv, *p_sim, *p_cath, *p_memh, *p_hidh, *p_w1h, *p_w2h;
    cudaGetSymbolAddress(&p_xinv, g_xinv);
    cudaGetSymbolAddress(&p_yinv, g_yinv);
    cudaGetSymbolAddress(&p_sim,  g_sim);
    cudaGetSymbolAddress(&p_cath, g_cat_h);
    cudaGetSymbolAddress(&p_memh, g_mem_h);
    cudaGetSymbolAddress(&p_hidh, g_hid_h);
    cudaGetSymbolAddress(&p_w1h,  g_w1_h);
    cudaGetSymbolAddress(&p_w2h,  g_w2_h);

    cudaFuncSetAttribute(tc_gemm<0>, cudaFuncAttributeMaxDynamicSharedMemorySize, GEMM_SMEM);
    cudaFuncSetAttribute(tc_gemm<1>, cudaFuncAttributeMaxDynamicSharedMemorySize, GEMM_SMEM);
    cudaFuncSetAttribute(tc_gemm<2>, cudaFuncAttributeMaxDynamicSharedMemorySize, GEMM_SMEM);

    // 1) fused prologue (norms + rounds) in ONE launch
    prep_kernel<<<PREP_BLOCKS, 256>>>(enc, mem, fc1w, fc2w);

    // 2) sim = (enc @ mem^T) * xinv[row] * yinv[col]  -> fp16
    tc_gemm<0><<<dim3(NM / 128, NB / 128), 128, GEMM_SMEM>>>(
        NM, ND, N2D, ND, NM,
        (const half*)p_cath, (const half*)p_memh,
        nullptr, (half*)p_sim,
        (const float*)p_xinv, (const float*)p_yinv, nullptr);

    // 3) sparsemax + sparse memory vector -> concat right half
    sparsemax_mv_kernel<<<NB, 256>>>(mem);

    // 4) hidden = relu(concat @ fc1w^T + b) -> fp16 store
    tc_gemm<1><<<dim3(NH / 128, NB / 128), 128, GEMM_SMEM>>>(
        NH, N2D, N2D, N2D, NH,
        (const half*)p_cath, (const half*)p_w1h,
        nullptr, (half*)p_hidh,
        nullptr, nullptr, fc1b);

    // 5) out = hidden @ fc2w^T + b  (padded N, store-guarded)
    tc_gemm<2><<<dim3(NOUTP / 128, NB / 128), 128, GEMM_SMEM>>>(
        NOUTP, NH, NH, NH, NOUT,
        (const half*)p_hidh, (const half*)p_w2h,
        out, nullptr,
        nullptr, nullptr, fc2b);
}

// round 16
// speedup vs baseline: 1.0415x; 1.0415x over previous
#include <cuda_runtime.h>
#include <cuda_fp16.h>
#include <cstdint>

// Problem constants
#define NB   4096   // batch B
#define NM   8192   // memory rows M
#define ND   1024   // dim D
#define NOUT 1000   // output classes
#define NOUTP 1024  // padded output cols
#define NH   4096   // 4*D hidden
#define N2D  2048   // 2*D concat width

// -------- scratch (device globals; no allocation allowed) --------
__device__ float g_xinv[NB];
__device__ float g_yinv[NM];
__device__ half  g_sim[(size_t)NB * NM];        // 64 MB (fp16 sims)
__device__ half  g_cat_h[(size_t)NB * N2D];     // 16 MB  [enc | mv] rounded
__device__ half  g_mem_h[(size_t)NM * ND];      // 16 MB
__device__ half  g_hid_h[(size_t)NB * NH];      // 32 MB
__device__ half  g_w1_h[(size_t)NH * N2D];      // 16 MB
__device__ half  g_w2_h[(size_t)NOUTP * NH];    // 8 MB (padded)

// ---------------------------------------------------------------
// helpers
// ---------------------------------------------------------------
__device__ __forceinline__ uint32_t cvta_smem(const void* p) {
    uint32_t a;
    asm("{ .reg .u64 t; cvta.to.shared.u64 t, %1; cvt.u32.u64 %0, t; }"
        : "=r"(a) : "l"(p));
    return a;
}

__device__ __forceinline__ void cp16(uint32_t dst, const void* src) {
    asm volatile("cp.async.cg.shared.global [%0], [%1], 16;" :: "r"(dst), "l"(src));
}

__device__ __forceinline__ void mma_fp16(float* d, const uint32_t* a, const uint32_t* b) {
    asm volatile(
        "mma.sync.aligned.m16n8k16.row.col.f32.f16.f16.f32 "
        "{%0,%1,%2,%3}, {%4,%5,%6,%7}, {%8,%9}, {%0,%1,%2,%3};"
        : "+f"(d[0]), "+f"(d[1]), "+f"(d[2]), "+f"(d[3])
        : "r"(a[0]), "r"(a[1]), "r"(a[2]), "r"(a[3]), "r"(b[0]), "r"(b[1]));
}

__device__ __forceinline__ void ldsm_x4(uint32_t* r, uint32_t addr) {
    asm volatile("ldmatrix.sync.aligned.m8n8.x4.shared.b16 {%0,%1,%2,%3}, [%4];"
                 : "=r"(r[0]), "=r"(r[1]), "=r"(r[2]), "=r"(r[3]) : "r"(addr));
}

// ---------------------------------------------------------------
// block reduce (256 threads)
// ---------------------------------------------------------------
__device__ __forceinline__ float blockReduceSum256(float v, float* red) {
    __syncthreads();
    #pragma unroll
    for (int o = 16; o > 0; o >>= 1) v += __shfl_down_sync(0xffffffffu, v, o);
    int warp = threadIdx.x >> 5, lane = threadIdx.x & 31;
    if (lane == 0) red[warp] = v;
    __syncthreads();
    if (warp == 0) {
        v = (lane < 8) ? red[lane] : 0.0f;
        #pragma unroll
        for (int o = 4; o > 0; o >>= 1) v += __shfl_down_sync(0xffffffffu, v, o);
        if (lane == 0) red[0] = v;
    }
    __syncthreads();
    return red[0];
}

// ---------------------------------------------------------------
// fused prologue: one launch covers
//   [0, 4096)        enc rows:  1/||x|| + fp16 round -> cat left
//   [4096, 12288)    mem rows:  1/||y|| + fp16 round
//   [12288, 20480)   fc1w round (1024 floats per block)
//   [20480, 21504)   fc2w round + zero-pad row
// ---------------------------------------------------------------
#define PREP_ENC_END 4096
#define PREP_MEM_END 12288
#define PREP_W1_END  20480
#define PREP_BLOCKS  21504

__global__ __launch_bounds__(256) void prep_kernel(
    const float* __restrict__ enc, const float* __restrict__ mem,
    const float* __restrict__ fc1w, const float* __restrict__ fc2w)
{
    __shared__ float red[8];
    const int bid = blockIdx.x, tid = threadIdx.x;

    if (bid < PREP_ENC_END) {
        const int row = bid;
        float4 v = ((const float4*)(enc + (size_t)row * ND))[tid];
        float s = v.x*v.x + v.y*v.y + v.z*v.z + v.w*v.w;
        s = blockReduceSum256(s, red);
        if (tid == 0) g_xinv[row] = rsqrtf(s + 1e-6f);
        half* ph = g_cat_h + (size_t)row * N2D + tid * 4;
        ph[0] = __float2half_rn(v.x); ph[1] = __float2half_rn(v.y);
        ph[2] = __float2half_rn(v.z); ph[3] = __float2half_rn(v.w);
    } else if (bid < PREP_MEM_END) {
        const int row = bid - PREP_ENC_END;
        float4 v = ((const float4*)(mem + (size_t)row * ND))[tid];
        float s = v.x*v.x + v.y*v.y + v.z*v.z + v.w*v.w;
        s = blockReduceSum256(s, red);
        if (tid == 0) g_yinv[row] = rsqrtf(s + 1e-6f);
        half* ph = g_mem_h + (size_t)row * ND + tid * 4;
        ph[0] = __float2half_rn(v.x); ph[1] = __float2half_rn(v.y);
        ph[2] = __float2half_rn(v.z); ph[3] = __float2half_rn(v.w);
    } else if (bid < PREP_W1_END) {
        const size_t i = (size_t)(bid - PREP_MEM_END) * 256 + tid;
        float4 v = ((const float4*)fc1w)[i];
        half* p = g_w1_h + i * 4;
        p[0] = __float2half_rn(v.x); p[1] = __float2half_rn(v.y);
        p[2] = __float2half_rn(v.z); p[3] = __float2half_rn(v.w);
    } else {
        const int row = bid - PREP_W1_END;   // 0..1023
        #pragma unroll
        for (int lq = 0; lq < 4; ++lq) {
            int idx = tid + 256 * lq;
            float4 v = make_float4(0.f, 0.f, 0.f, 0.f);
            if (row < NOUT) v = ((const float4*)(fc2w + (size_t)row * NH))[idx];
            half* p = g_w2_h + (size_t)row * NH + idx * 4;
            p[0] = __float2half_rn(v.x); p[1] = __float2half_rn(v.y);
            p[2] = __float2half_rn(v.z); p[3] = __float2half_rn(v.w);
        }
    }
}

// ---------------------------------------------------------------
// single-pass fp16 GEMM (mma.sync.m16n8k16 + ldmatrix):
//   C[M,N] = A[M,K] @ B[N,K]^T, fp32 accum
// 128x128 CTA tile, BK=64, 3-stage cp.async pipeline, 2 CTAs/SM,
// 256 threads (8 warps 2x4, 64x32 warp tiles).   [round-14 config]
// Coalesced tile loads (8 lanes per 128B row).
// EPI 0/1: smem-staged coalesced fp16 stores; EPI 2: guarded fp32.
// ---------------------------------------------------------------
#define BKE     64
#define ROW_B   144                      // 128 + 16 pad
#define A_T     (128 * ROW_B)            // 18432
#define B_T     (128 * ROW_B)            // 18432
#define STAGE_B (A_T + B_T)              // 36864
#define NSTAGE  3
#define GEMM_SMEM (NSTAGE * STAGE_B)     // 110592
#define OUT_SROW 136                     // staging stride in halves (272 B)

template<int EPI>
__global__ __launch_bounds__(256, 2) void tc_gemm(
    int N, int K, int lda, int ldb, int Nout,
    const half* __restrict__ A0, const half* __restrict__ B0,
    float* __restrict__ C, half* __restrict__ Ch,
    const float* __restrict__ xinv, const float* __restrict__ yinv,
    const float* __restrict__ bias)
{
    extern __shared__ __align__(1024) char smraw[];
    const uint32_t smemU = cvta_smem(smraw);

    const int tid  = threadIdx.x;
    const int lane = tid & 31;
    const int wid  = tid >> 5;
    const int wm   = wid & 1;          // 0..1 (64-row block)
    const int wn   = wid >> 1;         // 0..3 (32-col block)
    const int row0 = blockIdx.y * 128;
    const int col0 = blockIdx.x * 128;

    const int nkc = K / BKE;

    // Coalesced global->smem: 8 lanes per row (16B each)
    const int wr  = tid >> 3;          // 0..31 base row
    const int lc8 = tid & 7;
    const uint32_t aBase = smemU + wr * ROW_B + lc8 * 16;
    const uint32_t bBase = smemU + A_T + wr * ROW_B + lc8 * 16;

    auto do_load = [&](int ck, int s) {
        const uint32_t so = s * STAGE_B;
        const half* ga = A0 + (size_t)(row0 + wr) * lda + ck * BKE + lc8 * 8;
        const half* gb = B0 + (size_t)(col0 + wr) * ldb + ck * BKE + lc8 * 8;
        #pragma unroll
        for (int i = 0; i < 4; ++i) {
            cp16(aBase + so + i * (32 * ROW_B), ga + (size_t)(32 * i) * lda);
            cp16(bBase + so + i * (32 * ROW_B), gb + (size_t)(32 * i) * ldb);
        }
    };

    float acc[4][4][4];
    #pragma unroll
    for (int mt = 0; mt < 4; ++mt)
        #pragma unroll
        for (int nt = 0; nt < 4; ++nt)
            #pragma unroll
            for (int c = 0; c < 4; ++c) acc[mt][nt][c] = 0.0f;

    do_load(0, 0);
    asm volatile("cp.async.commit_group;" ::: "memory");
    do_load(1, 1);
    asm volatile("cp.async.commit_group;" ::: "memory");

    // ldmatrix lane bases
    const uint32_t aFragBase = smemU + (wm * 64 + (lane & 15)) * ROW_B + (lane >> 4) * 16;
    const uint32_t bFragBase = smemU + A_T +
        (wn * 32 + (lane & 7) + ((lane >> 4) & 1) * 8) * ROW_B + ((lane >> 3) & 1) * 16;

    for (int it = 0; it < nkc; ++it) {
        if (it + 2 < nkc) {
            asm volatile("cp.async.wait_group 1;" ::: "memory");
        } else {
            asm volatile("cp.async.wait_group 0;" ::: "memory");
        }
        __syncthreads();
        if (it + 2 < nkc) {
            do_load(it + 2, (it + 2) % NSTAGE);
            asm volatile("cp.async.commit_group;" ::: "memory");
        }

        const uint32_t so = (it % NSTAGE) * STAGE_B;

        #pragma unroll
        for (int ks = 0; ks < 4; ++ks) {
            const uint32_t ko = ks * 32;
            uint32_t bfr[8];   // 4 n-tiles x 2 regs
            #pragma unroll
            for (int p = 0; p < 2; ++p)
                ldsm_x4(&bfr[4 * p], bFragBase + so + p * (16 * ROW_B) + ko);

            uint32_t afr[4][4];
            #pragma unroll
            for (int mt = 0; mt < 4; ++mt)
                ldsm_x4(afr[mt], aFragBase + so + mt * (16 * ROW_B) + ko);
            #pragma unroll
            for (int mt = 0; mt < 4; ++mt)
                #pragma unroll
                for (int nt = 0; nt < 4; ++nt)
                    mma_fp16(acc[mt][nt], afr[mt], &bfr[nt * 2]);
        }
    }

    // epilogue
    const int r = lane >> 2;
    const int q = lane & 3;

    if (EPI == 2) {
        #pragma unroll
        for (int mt = 0; mt < 4; ++mt) {
            const int gr0 = row0 + wm * 64 + mt * 16 + r;
            #pragma unroll
            for (int half_ = 0; half_ < 2; ++half_) {
                const int gr = gr0 + half_ * 8;
                #pragma unroll
                for (int nt = 0; nt < 4; ++nt) {
                    const int gc = col0 + wn * 32 + nt * 8 + q * 2;
                    if (gc < Nout) {
                        float2 o = make_float2(acc[mt][nt][half_ * 2 + 0] + bias[gc],
                                               acc[mt][nt][half_ * 2 + 1] + bias[gc + 1]);
                        *(float2*)(C + (size_t)gr * Nout + gc) = o;
                    }
                }
            }
        }
    } else {
        __syncthreads();
        half* stg = (half*)smraw;
        #pragma unroll
        for (int mt = 0; mt < 4; ++mt) {
            const int lr0 = wm * 64 + mt * 16 + r;
            #pragma unroll
            for (int half_ = 0; half_ < 2; ++half_) {
                const int lr = lr0 + half_ * 8;
                float xr = 0.0f;
                if (EPI == 0) xr = xinv[row0 + lr];
                #pragma unroll
                for (int nt = 0; nt < 4; ++nt) {
                    const int lcL = wn * 32 + nt * 8 + q * 2;
                    float v0 = acc[mt][nt][half_ * 2 + 0];
                    float v1 = acc[mt][nt][half_ * 2 + 1];
                    __half2 hh;
                    const int gc = col0 + lcL;
                    if (EPI == 0) {
                        hh.x = __float2half_rn(v0 * xr * yinv[gc]);
                        hh.y = __float2half_rn(v1 * xr * yinv[gc + 1]);
                    } else {
                        hh.x = __float2half_rn(fmaxf(v0 + bias[gc], 0.0f));
                        hh.y = __float2half_rn(fmaxf(v1 + bias[gc + 1], 0.0f));
                    }
                    *(__half2*)(stg + lr * OUT_SROW + lcL) = hh;
                }
            }
        }
        __syncthreads();
        // coalesced: 128 rows x 16 uint4 (256B/row)
        #pragma unroll
        for (int i = 0; i < 8; ++i) {
            const int idx  = tid + i * 256;
            const int rrow = idx >> 4;
            const int slot = idx & 15;
            uint4 v = *(const uint4*)(stg + rrow * OUT_SROW + slot * 8);
            *(uint4*)(Ch + (size_t)(row0 + rrow) * N + col0 + slot * 8) = v;
        }
    }
}

// ---------------------------------------------------------------
// Fused sparsemax (Michelot, sort-free, register-resident) + sparse
// memory-vector gather.  z input is fp16 (g_sim); math in fp32 regs.
// Gather reads fp16 g_mem_h (2KB/row) -- halves L2 gather traffic;
// precision-neutral since mv is rounded to fp16 anyway.
// ---------------------------------------------------------------
#define SPX_CAP 4096
__global__ __launch_bounds__(256) void sparsemax_mv_kernel() {
    __shared__ __align__(16) half zh[NM];    // 16 KB
    __shared__ unsigned short idxs[SPX_CAP]; // 8 KB
    __shared__ float redS[8];
    __shared__ float redC[8];
    __shared__ int   wtot[8];
    __shared__ int   wpre[8];
    __shared__ float tau_sh;
    __shared__ int   cprev_sh;
    __shared__ int   done_sh;

    const int row = blockIdx.x;
    const int tid = threadIdx.x;
    const int warp = tid >> 5, lane = tid & 31;

    float zr[32];
    {
        const uint4* src = (const uint4*)(g_sim + (size_t)row * NM);
        #pragma unroll
        for (int l = 0; l < 4; ++l) {
            uint4 raw = src[tid + l * 256];
            ((uint4*)zh)[tid + l * 256] = raw;
            const __half2* hp = (const __half2*)&raw;
            #pragma unroll
            for (int k = 0; k < 4; ++k) {
                float2 f = __half22float2(hp[k]);
                zr[l * 8 + 2 * k]     = f.x;
                zr[l * 8 + 2 * k + 1] = f.y;
            }
        }
    }
    __syncthreads();

    {
        float s = 0.0f;
        #pragma unroll
        for (int i = 0; i < 32; ++i) s += zr[i];
        s = blockReduceSum256(s, redS);
        if (tid == 0) {
            tau_sh = (s - 1.0f) / (float)NM;
            cprev_sh = NM;
            done_sh = 0;
        }
        __syncthreads();
    }

    for (int it = 0; it < 64; ++it) {
        float tau = tau_sh;
        float ls = 0.0f, lc = 0.0f;
        #pragma unroll
        for (int i = 0; i < 32; ++i)
            if (zr[i] > tau) { ls += zr[i]; lc += 1.0f; }
        #pragma unroll
        for (int o = 16; o > 0; o >>= 1) {
            ls += __shfl_down_sync(0xffffffffu, ls, o);
            lc += __shfl_down_sync(0xffffffffu, lc, o);
        }
        if (lane == 0) { redS[warp] = ls; redC[warp] = lc; }
        __syncthreads();
        if (tid == 0) {
            float S = 0.0f, Cc = 0.0f;
            #pragma unroll
            for (int w = 0; w < 8; ++w) { S += redS[w]; Cc += redC[w]; }
            int c = (int)(Cc + 0.5f);
            if (c == cprev_sh || c <= 0) done_sh = 1;
            else { cprev_sh = c; tau_sh = (S - 1.0f) / (float)c; }
        }
        __syncthreads();
        if (done_sh) break;
    }
    const float tau = tau_sh;

    int mycnt = 0;
    #pragma unroll
    for (int i = 0; i < 32; ++i)
        if (zr[i] > tau) mycnt++;

    int csum = mycnt;
    #pragma unroll
    for (int o = 1; o < 32; o <<= 1) {
        int n = __shfl_up_sync(0xffffffffu, csum, o);
        if (lane >= o) csum += n;
    }
    if (lane == 31) wtot[warp] = csum;
    __syncthreads();
    if (warp == 0 && lane < 8) {
        int t = wtot[lane];
        #pragma unroll
        for (int o = 1; o < 8; o <<= 1) {
            int n = __shfl_up_sync(0x000000ffu, t, o);
            if (lane >= o) t += n;
        }
        wpre[lane] = t;
    }
    __syncthreads();
    const int nnz = wpre[7];
    if (nnz <= SPX_CAP) {
        int off = (warp ? wpre[warp - 1] : 0) + csum - mycnt;
        #pragma unroll
        for (int l = 0; l < 4; ++l) {
            int base = 8 * (tid + l * 256);
            #pragma unroll
            for (int j = 0; j < 8; ++j)
                if (zr[l * 8 + j] > tau) idxs[off++] = (unsigned short)(base + j);
        }
    }
    __syncthreads();

    // sparse MV from fp16 memory: thread covers cols [4*tid, 4*tid+4)
    float4 acc = make_float4(0.f, 0.f, 0.f, 0.f);
    if (nnz <= SPX_CAP) {
        #pragma unroll 4
        for (int j = 0; j < nnz; ++j) {
            int m = idxs[j];
            float w = __half2float(zh[m]) - tau;
            uint2 raw = *(const uint2*)(g_mem_h + (size_t)m * ND + tid * 4);
            float2 v01 = __half22float2(*(const __half2*)&raw.x);
            float2 v23 = __half22float2(*(const __half2*)&raw.y);
            acc.x += w * v01.x; acc.y += w * v01.y;
            acc.z += w * v23.x; acc.w += w * v23.y;
        }
    } else {
        for (int m = 0; m < NM; ++m) {
            float w = __half2float(zh[m]) - tau;
            if (w > 0.0f) {
                uint2 raw = *(const uint2*)(g_mem_h + (size_t)m * ND + tid * 4);
                float2 v01 = __half22float2(*(const __half2*)&raw.x);
                float2 v23 = __half22float2(*(const __half2*)&raw.y);
                acc.x += w * v01.x; acc.y += w * v01.y;
                acc.z += w * v23.x; acc.w += w * v23.y;
            }
        }
    }
    half* ph = g_cat_h + (size_t)row * N2D + ND + tid * 4;
    ph[0] = __float2half_rn(acc.x); ph[1] = __float2half_rn(acc.y);
    ph[2] = __float2half_rn(acc.z); ph[3] = __float2half_rn(acc.w);
}

// ---------------------------------------------------------------
// launch
// ---------------------------------------------------------------
extern "C" void kernel_launch(void* const* d_in, const int* in_sizes, int n_in,
                              void* d_out, int out_size) {
    const float* enc  = (const float*)d_in[0];  // [4096,1024]
    const float* mem  = (const float*)d_in[1];  // [8192,1024]
    const float* fc1w = (const float*)d_in[2];  // [4096,2048]
    const float* fc1b = (const float*)d_in[3];  // [4096]
    const float* fc2w = (const float*)d_in[4];  // [1000,4096]
    const float* fc2b = (const float*)d_in[5];  // [1000]
    float* out = (float*)d_out;                 // [4096,1000]

    void *p_xinv, *p_yinv, *p_sim, *p_cath, *p_memh, *p_hidh, *p_w1h, *p_w2h;
    cudaGetSymbolAddress(&p_xinv, g_xinv);
    cudaGetSymbolAddress(&p_yinv, g_yinv);
    cudaGetSymbolAddress(&p_sim,  g_sim);
    cudaGetSymbolAddress(&p_cath, g_cat_h);
    cudaGetSymbolAddress(&p_memh, g_mem_h);
    cudaGetSymbolAddress(&p_hidh, g_hid_h);
    cudaGetSymbolAddress(&p_w1h,  g_w1_h);
    cudaGetSymbolAddress(&p_w2h,  g_w2_h);

    cudaFuncSetAttribute(tc_gemm<0>, cudaFuncAttributeMaxDynamicSharedMemorySize, GEMM_SMEM);
    cudaFuncSetAttribute(tc_gemm<1>, cudaFuncAttributeMaxDynamicSharedMemorySize, GEMM_SMEM);
    cudaFuncSetAttribute(tc_gemm<2>, cudaFuncAttributeMaxDynamicSharedMemorySize, GEMM_SMEM);

    // 1) fused prologue (norms + rounds) in ONE launch
    prep_kernel<<<PREP_BLOCKS, 256>>>(enc, mem, fc1w, fc2w);

    // 2) sim = (enc @ mem^T) * xinv[row] * yinv[col]  -> fp16
    tc_gemm<0><<<dim3(NM / 128, NB / 128), 256, GEMM_SMEM>>>(
        NM, ND, N2D, ND, NM,
        (const half*)p_cath, (const half*)p_memh,
        nullptr, (half*)p_sim,
        (const float*)p_xinv, (const float*)p_yinv, nullptr);

    // 3) sparsemax + sparse memory vector -> concat right half
    sparsemax_mv_kernel<<<NB, 256>>>();

    // 4) hidden = relu(concat @ fc1w^T + b) -> fp16 store
    tc_gemm<1><<<dim3(NH / 128, NB / 128), 256, GEMM_SMEM>>>(
        NH, N2D, N2D, N2D, NH,
        (const half*)p_cath, (const half*)p_w1h,
        nullptr, (half*)p_hidh,
        nullptr, nullptr, fc1b);

    // 5) out = hidden @ fc2w^T + b  (padded N, store-guarded)
    tc_gemm<2><<<dim3(NOUTP / 128, NB / 128), 256, GEMM_SMEM>>>(
        NOUTP, NH, NH, NH, NOUT,
        (const half*)p_hidh, (const half*)p_w2h,
        out, nullptr,
        nullptr, nullptr, fc2b);
}